// round 3
// baseline (speedup 1.0000x reference)
#include <cuda_runtime.h>
#include <cstddef>

// Problem constants (fixed by the reference: N=1024, D=16, E=16384)
#define NNODES 1024
#define D_DIM  16
#define NM     16384          // N * D
#define EMAX   16384

// ---------------- scratch (device globals: allocation-free) ----------------
__device__ float g_triu[(size_t)EMAX * 256];        // 16.8 MB: -dr*dc*(A^T B), final values
__device__ float g_diag[(size_t)NNODES * 256];      //  1.0 MB: dinv^2-scaled Gram sums
__device__ int   g_map [(size_t)NNODES * NNODES];   //  4.0 MB: (bi,bj) -> +-(e+1), 0 = empty
__device__ int   g_idx_stride;                      // 1 = int32 edge_index, 2 = int64 LE

// Robust dtype detection. The first 65536 int32 words are valid under both
// dtypes. int64 LE: every odd word is a high word of a value < 1024 -> 0.
// int32: odd words include edge_index[0][16384..] = col values, all >= 1.
__global__ void detect_idx_kernel(const int* __restrict__ eidx32) {
    __shared__ int any_nonzero;
    if (threadIdx.x == 0) any_nonzero = 0;
    __syncthreads();
    int local = 0;
    for (int w = 1 + 2 * threadIdx.x; w < 65536; w += 2 * blockDim.x)
        local |= eidx32[w];
    if (local) atomicOr(&any_nonzero, 1);
    __syncthreads();
    if (threadIdx.x == 0) g_idx_stride = any_nonzero ? 1 : 2;
}

// Zero g_map (1M ints) and g_diag (256K floats). ~1 us.
__global__ void zero_scratch_kernel() {
    const int tid = blockIdx.x * blockDim.x + threadIdx.x;
    const int total = NNODES * NNODES / 4;              // int4 granularity over map
    if (tid < total) ((int4*)g_map)[tid] = make_int4(0, 0, 0, 0);
    if (tid < NNODES * 256 / 4) ((float4*)g_diag)[tid] = make_float4(0.f, 0.f, 0.f, 0.f);
}

// Pass 1: one CTA (256 threads) per undirected edge.
//   g_triu[e]    = -dinv[r]*dinv[c] * (A^T B)      (final scaled value)
//   g_diag[r]   += dinv[r]^2 * (A^T A)             (atomic, L2-resident scratch)
//   g_diag[c]   += dinv[c]^2 * (B^T B)
//   g_map[r,c]   = e+1 ; g_map[c,r] = -(e+1)
__global__ void edge_compute_kernel(const float* __restrict__ degrees,
                                    const float* __restrict__ maps,
                                    const int*   __restrict__ eidx32,
                                    int E) {
    __shared__ float Asm[256];
    __shared__ float Bsm[256];

    const int e   = blockIdx.x;
    const int tid = threadIdx.x;
    const int j   = tid >> 4;
    const int k   = tid & 15;

    const int stride = g_idx_stride;
    const int r = eidx32[(size_t)e * stride];
    const int c = eidx32[(size_t)(2 * E + e) * stride];

    Asm[tid] = maps[(size_t)e * 256 + tid];
    Bsm[tid] = maps[((size_t)e + E) * 256 + tid];
    __syncthreads();

    float t = 0.f, g1 = 0.f, g2 = 0.f;
    #pragma unroll
    for (int i = 0; i < 16; ++i) {
        const float aj = Asm[i * 16 + j];
        const float ak = Asm[i * 16 + k];
        const float bj = Bsm[i * 16 + j];
        const float bk = Bsm[i * 16 + k];
        t  += aj * bk;     // (A^T B)[j,k]
        g1 += aj * ak;     // (A^T A)[j,k]
        g2 += bj * bk;     // (B^T B)[j,k]
    }

    const float dr = rsqrtf(degrees[r] * (float)D_DIM + 1.0f);
    const float dc = rsqrtf(degrees[c] * (float)D_DIM + 1.0f);

    g_triu[(size_t)e * 256 + tid] = -(dr * dc) * t;
    atomicAdd(&g_diag[(size_t)r * 256 + tid], (dr * dr) * g1);
    atomicAdd(&g_diag[(size_t)c * 256 + tid], (dc * dc) * g2);

    if (tid == 0) {
        g_map[(size_t)r * NNODES + c] = e + 1;
        g_map[(size_t)c * NNODES + r] = -(e + 1);
    }
}

// Pass 2: single streaming pass over the full 1.07 GB output.
// CTA bi owns block-row bi (16 output rows). Map row cached in smem.
// float4 stores; ~97% of blocks are plain zeros (memset-rate path).
__global__ void __launch_bounds__(256) write_output_kernel(float* __restrict__ out) {
    __shared__ int mrow[NNODES];

    const int bi = blockIdx.x;
    const int t  = threadIdx.x;

    for (int i = t; i < NNODES; i += 256)
        mrow[i] = g_map[(size_t)bi * NNODES + i];
    __syncthreads();

    #pragma unroll 1
    for (int a = 0; a < 16; ++a) {
        const size_t rowbase = (size_t)(bi * 16 + a) * NM;
        #pragma unroll 4
        for (int it = 0; it < 16; ++it) {
            const int col = (it * 256 + t) * 4;   // float4-aligned column
            const int bj  = col >> 4;
            const int kk  = col & 15;
            float4 v = make_float4(0.f, 0.f, 0.f, 0.f);
            if (bj == bi) {
                v = *(const float4*)&g_diag[(size_t)bi * 256 + a * 16 + kk];
            } else {
                const int m = mrow[bj];
                if (m > 0) {
                    v = *(const float4*)&g_triu[(size_t)(m - 1) * 256 + a * 16 + kk];
                } else if (m < 0) {
                    // tril block = transpose of stored triu block
                    const float* p = &g_triu[(size_t)(-m - 1) * 256];
                    v.x = p[(kk + 0) * 16 + a];
                    v.y = p[(kk + 1) * 16 + a];
                    v.z = p[(kk + 2) * 16 + a];
                    v.w = p[(kk + 3) * 16 + a];
                }
            }
            *(float4*)&out[rowbase + col] = v;
        }
    }
}

extern "C" void kernel_launch(void* const* d_in, const int* in_sizes, int n_in,
                              void* d_out, int out_size) {
    // Inputs (metadata order): adj_mat [N*N f32], degrees [N f32],
    // maps [2E*16*16 f32], edge_index [2*2E int]
    const float* degrees = (const float*)d_in[1];
    const float* maps    = (const float*)d_in[2];
    const int*   eidx32  = (const int*)d_in[3];
    float*       out     = (float*)d_out;

    const int E = in_sizes[2] / (2 * 256);   // maps has 2E blocks of 256 floats

    detect_idx_kernel<<<1, 256>>>(eidx32);
    zero_scratch_kernel<<<(NNODES * NNODES / 4 + 255) / 256, 256>>>();
    edge_compute_kernel<<<E, 256>>>(degrees, maps, eidx32, E);
    write_output_kernel<<<NNODES, 256>>>(out);
}

// round 4
// speedup vs baseline: 1.4024x; 1.4024x over previous
#include <cuda_runtime.h>
#include <cstddef>

// Problem constants (fixed by the reference: N=1024, D=16, E=16384)
#define NNODES 1024
#define D_DIM  16
#define NM     16384          // N * D
#define EMAX   16384

// ---------------- scratch (device globals: allocation-free) ----------------
__device__ float g_triu[(size_t)EMAX * 256];    // 16.8 MB: -dr*dc*(A^T B), final values
__device__ float g_diag[(size_t)NNODES * 256];  //  1.0 MB: dinv^2-scaled Gram sums
__device__ int   g_idx_stride;                  // 1 = int32 edge_index, 2 = int64 LE

// Zero g_diag and detect edge_index dtype with a single deterministic probe:
// int32 layout (2,32768): word 32769 = edge_index[1][1] = col[1] >= 1 (r < c).
// int64 LE layout: word 32769 = high half of edge_index[0][16384], value < 1024 -> 0.
__global__ void zero_scratch_kernel(const int* __restrict__ eidx32) {
    const int tid = blockIdx.x * blockDim.x + threadIdx.x;
    if (tid < NNODES * 256 / 4)
        ((float4*)g_diag)[tid] = make_float4(0.f, 0.f, 0.f, 0.f);
    if (tid == 0)
        g_idx_stride = (eidx32[32769] != 0) ? 1 : 2;
}

// Pass 1: 4 edges per CTA, 64 threads per edge, 4 outputs per thread.
// Per i-iteration: 8 LDS feed 12 FMAs (2 loads/output vs 4 in the naive version).
//   g_triu[e]  = -dinv[r]*dinv[c] * (A^T B)   (final scaled value)
//   g_diag[r] += dinv[r]^2 * (A^T A)          (atomic, 1 MB L2-resident scratch)
//   g_diag[c] += dinv[c]^2 * (B^T B)
__global__ void __launch_bounds__(256) edge_compute_kernel(
        const float* __restrict__ degrees,
        const float* __restrict__ maps,
        const int*   __restrict__ eidx32,
        int E) {
    __shared__ float Asm[4][256];
    __shared__ float Bsm[4][256];

    const int tid = threadIdx.x;
    const int g   = tid >> 6;          // edge slot 0..3 in this CTA
    const int lt  = tid & 63;
    const int e   = blockIdx.x * 4 + g;

    const int stride = g_idx_stride;
    const int r = eidx32[(size_t)e * stride];
    const int c = eidx32[(size_t)(2 * E + e) * stride];

    #pragma unroll
    for (int i = lt; i < 256; i += 64) {
        Asm[g][i] = maps[(size_t)e * 256 + i];
        Bsm[g][i] = maps[((size_t)e + E) * 256 + i];
    }
    __syncthreads();

    const int j0 = lt >> 3;            // 0..7   (rows j0, j0+8)
    const int k0 = lt & 7;             // 0..7   (cols k0, k0+8)

    float t00 = 0.f, t01 = 0.f, t10 = 0.f, t11 = 0.f;
    float p00 = 0.f, p01 = 0.f, p10 = 0.f, p11 = 0.f;   // A^T A
    float q00 = 0.f, q01 = 0.f, q10 = 0.f, q11 = 0.f;   // B^T B

    #pragma unroll
    for (int i = 0; i < 16; ++i) {
        const float aj0 = Asm[g][i * 16 + j0];
        const float aj1 = Asm[g][i * 16 + j0 + 8];
        const float ak0 = Asm[g][i * 16 + k0];
        const float ak1 = Asm[g][i * 16 + k0 + 8];
        const float bj0 = Bsm[g][i * 16 + j0];
        const float bj1 = Bsm[g][i * 16 + j0 + 8];
        const float bk0 = Bsm[g][i * 16 + k0];
        const float bk1 = Bsm[g][i * 16 + k0 + 8];
        t00 += aj0 * bk0;  t01 += aj0 * bk1;  t10 += aj1 * bk0;  t11 += aj1 * bk1;
        p00 += aj0 * ak0;  p01 += aj0 * ak1;  p10 += aj1 * ak0;  p11 += aj1 * ak1;
        q00 += bj0 * bk0;  q01 += bj0 * bk1;  q10 += bj1 * bk0;  q11 += bj1 * bk1;
    }

    const float dr = rsqrtf(degrees[r] * (float)D_DIM + 1.0f);
    const float dc = rsqrtf(degrees[c] * (float)D_DIM + 1.0f);
    const float s  = -(dr * dc);
    const float sr = dr * dr;
    const float sc = dc * dc;

    float* tr = &g_triu[(size_t)e * 256];
    tr[j0 * 16 + k0]            = s * t00;
    tr[j0 * 16 + k0 + 8]        = s * t01;
    tr[(j0 + 8) * 16 + k0]      = s * t10;
    tr[(j0 + 8) * 16 + k0 + 8]  = s * t11;

    float* dgr = &g_diag[(size_t)r * 256];
    atomicAdd(&dgr[j0 * 16 + k0],           sr * p00);
    atomicAdd(&dgr[j0 * 16 + k0 + 8],       sr * p01);
    atomicAdd(&dgr[(j0 + 8) * 16 + k0],     sr * p10);
    atomicAdd(&dgr[(j0 + 8) * 16 + k0 + 8], sr * p11);

    float* dgc = &g_diag[(size_t)c * 256];
    atomicAdd(&dgc[j0 * 16 + k0],           sc * q00);
    atomicAdd(&dgc[j0 * 16 + k0 + 8],       sc * q01);
    atomicAdd(&dgc[(j0 + 8) * 16 + k0],     sc * q10);
    atomicAdd(&dgc[(j0 + 8) * 16 + k0 + 8], sc * q11);
}

// Inject: runs after the memset. Pure scatter of the 3% nonzero blocks.
// CTA e < E: write triu block (r,c) and transposed tril block (c,r).
// CTA e >= E: write 16 diag blocks from g_diag.
__global__ void __launch_bounds__(256) inject_kernel(
        const int* __restrict__ eidx32,
        float*     __restrict__ out,
        int E) {
    const int tid = threadIdx.x;
    const int j   = tid >> 4;
    const int k   = tid & 15;
    const int e   = blockIdx.x;

    if (e < E) {
        __shared__ float Tsm[16][17];
        const int stride = g_idx_stride;
        const int r = eidx32[(size_t)e * stride];
        const int c = eidx32[(size_t)(2 * E + e) * stride];

        const float v = g_triu[(size_t)e * 256 + tid];
        out[(size_t)(r * 16 + j) * NM + c * 16 + k] = v;

        Tsm[j][k] = v;
        __syncthreads();
        out[(size_t)(c * 16 + j) * NM + r * 16 + k] = Tsm[k][j];
    } else {
        const int n0 = (e - E) * 16;
        #pragma unroll
        for (int nn = 0; nn < 16; ++nn) {
            const int node = n0 + nn;
            out[(size_t)(node * 16 + j) * NM + node * 16 + k] =
                g_diag[(size_t)node * 256 + tid];
        }
    }
}

extern "C" void kernel_launch(void* const* d_in, const int* in_sizes, int n_in,
                              void* d_out, int out_size) {
    // Inputs (metadata order): adj_mat [N*N f32], degrees [N f32],
    // maps [2E*16*16 f32], edge_index [2*2E int]
    const float* degrees = (const float*)d_in[1];
    const float* maps    = (const float*)d_in[2];
    const int*   eidx32  = (const int*)d_in[3];
    float*       out     = (float*)d_out;

    const int E = in_sizes[2] / (2 * 256);   // maps has 2E blocks of 256 floats

    // 1) Zero the 1 MB diag scratch + single-word dtype probe
    zero_scratch_kernel<<<(NNODES * 256 / 4 + 255) / 256, 256>>>(eidx32);

    // 2) Compute all scaled blocks into scratch (no touches of `out`)
    edge_compute_kernel<<<E / 4, 256>>>(degrees, maps, eidx32, E);

    // 3) Pure bandwidth-optimal zero fill of the 1.07 GB output
    cudaMemsetAsync(d_out, 0, (size_t)out_size * sizeof(float), 0);

    // 4) Scatter the ~3% nonzero blocks (triu + tril + diag)
    inject_kernel<<<E + NNODES / 16, 256>>>(eidx32, out, E);
}